// round 2
// baseline (speedup 1.0000x reference)
#include <cuda_runtime.h>
#include <cstddef>

// Problem constants
constexpr int DM = 1024;   // d_model
constexpr int SQ = 2048;   // seq len
constexpr int BB = 2;      // batch
constexpr int NH = 16;     // heads
constexpr int HD = 64;     // head dim
constexpr int MT = BB * SQ; // 4096 total rows

// Scratch (static device globals — no cudaMalloc allowed)
__device__ float g_q[BB * SQ * DM];
__device__ float g_k[BB * SQ * DM];
__device__ float g_v[BB * SQ * DM];
__device__ float g_attn[BB * SQ * DM];

// ---------------------------------------------------------------------------
// C[m][n] = sum_k A[m][k] * W[n][k]   (A: [MT][DM] row-major, W: [DM][DM] row-major)
// 128x128 tile, BK=16, 256 threads, 8x8 per thread (split-64 mapping).
// ---------------------------------------------------------------------------
__global__ __launch_bounds__(256) void gemm_nt(const float* __restrict__ A,
                                               const float* __restrict__ W,
                                               float* __restrict__ C) {
    constexpr int K = DM, N = DM;
    constexpr int GBM = 128, GBK = 16;
    __shared__ float As[GBK][GBM];
    __shared__ float Bs[GBK][GBM];

    const int tid = threadIdx.x;
    const int ty = tid >> 4;        // 0..15
    const int tx = tid & 15;        // 0..15
    const int m0 = blockIdx.y * GBM;
    const int n0 = blockIdx.x * GBM;
    const int lr = tid >> 2;        // 0..63
    const int lc = (tid & 3) * 4;   // 0,4,8,12

    float acc[8][8];
#pragma unroll
    for (int i = 0; i < 8; i++)
#pragma unroll
        for (int j = 0; j < 8; j++) acc[i][j] = 0.0f;

    for (int k0 = 0; k0 < K; k0 += GBK) {
#pragma unroll
        for (int p = 0; p < 2; p++) {
            int r = lr + p * 64;
            float4 av = *(const float4*)(A + (size_t)(m0 + r) * K + k0 + lc);
            float4 wv = *(const float4*)(W + (size_t)(n0 + r) * K + k0 + lc);
            As[lc + 0][r] = av.x; As[lc + 1][r] = av.y;
            As[lc + 2][r] = av.z; As[lc + 3][r] = av.w;
            Bs[lc + 0][r] = wv.x; Bs[lc + 1][r] = wv.y;
            Bs[lc + 2][r] = wv.z; Bs[lc + 3][r] = wv.w;
        }
        __syncthreads();
#pragma unroll
        for (int kk = 0; kk < GBK; kk++) {
            float4 a0 = *(const float4*)&As[kk][ty * 4];
            float4 a1 = *(const float4*)&As[kk][64 + ty * 4];
            float4 b0 = *(const float4*)&Bs[kk][tx * 4];
            float4 b1 = *(const float4*)&Bs[kk][64 + tx * 4];
            float ar[8] = {a0.x, a0.y, a0.z, a0.w, a1.x, a1.y, a1.z, a1.w};
            float br[8] = {b0.x, b0.y, b0.z, b0.w, b1.x, b1.y, b1.z, b1.w};
#pragma unroll
            for (int i = 0; i < 8; i++)
#pragma unroll
                for (int j = 0; j < 8; j++) acc[i][j] += ar[i] * br[j];
        }
        __syncthreads();
    }

#pragma unroll
    for (int i = 0; i < 8; i++) {
        int row = m0 + ((i < 4) ? (ty * 4 + i) : (64 + ty * 4 + (i - 4)));
        float4 o0 = make_float4(acc[i][0], acc[i][1], acc[i][2], acc[i][3]);
        float4 o1 = make_float4(acc[i][4], acc[i][5], acc[i][6], acc[i][7]);
        *(float4*)(C + (size_t)row * N + n0 + tx * 4)      = o0;
        *(float4*)(C + (size_t)row * N + n0 + 64 + tx * 4) = o1;
    }
}

// ---------------------------------------------------------------------------
// Flash-style causal attention over [B,S,D] Q/K/V (head h occupies cols h*64..).
// One CTA per (qtile of 64 rows, head, batch). 256 threads, 4x4 per thread.
// Q,K stored k-major ([dh][row]) in smem so score-loop reads are conflict-free.
// P tile reuses the K buffer (48KB static smem total).
// ---------------------------------------------------------------------------
__global__ __launch_bounds__(256) void attn_kernel(const float* __restrict__ Q,
                                                   const float* __restrict__ Kg,
                                                   const float* __restrict__ V,
                                                   float* __restrict__ O) {
    __shared__ float Qs[64][64];  // [dh][row]
    __shared__ float KP[64][64];  // K as [dh][col], then reused as P [row][col]
    __shared__ float Vs[64][64];  // [key][dh]

    const int tid = threadIdx.x;
    const int ty = tid >> 4;       // 0..15 -> rows ty*4..ty*4+3
    const int tx = tid & 15;       // 0..15 -> cols tx*4..tx*4+3
    const int qt = blockIdx.x;
    const int h  = blockIdx.y;
    const int b  = blockIdx.z;

    const int lr = tid >> 4;           // 0..15
    const int lc = (tid & 15) * 4;     // 0..60

    const float* qb = Q + ((size_t)(b * SQ + qt * 64)) * DM + h * HD;

    // Load Q tile transposed -> Qs[dh][row]
#pragma unroll
    for (int p = 0; p < 4; p++) {
        int r = lr + p * 16;
        float4 v = *(const float4*)(qb + (size_t)r * DM + lc);
        Qs[lc + 0][r] = v.x; Qs[lc + 1][r] = v.y;
        Qs[lc + 2][r] = v.z; Qs[lc + 3][r] = v.w;
    }

    float m_i[4], l_i[4], acc[4][4];
#pragma unroll
    for (int i = 0; i < 4; i++) {
        m_i[i] = -1e30f;
        l_i[i] = 0.0f;
#pragma unroll
        for (int j = 0; j < 4; j++) acc[i][j] = 0.0f;
    }
    __syncthreads();

    for (int kt = 0; kt <= qt; kt++) {
        const float* kb = Kg + ((size_t)(b * SQ + kt * 64)) * DM + h * HD;
        const float* vb = V  + ((size_t)(b * SQ + kt * 64)) * DM + h * HD;
#pragma unroll
        for (int p = 0; p < 4; p++) {
            int r = lr + p * 16;
            float4 kv = *(const float4*)(kb + (size_t)r * DM + lc);
            KP[lc + 0][r] = kv.x; KP[lc + 1][r] = kv.y;
            KP[lc + 2][r] = kv.z; KP[lc + 3][r] = kv.w;
            float4 vv = *(const float4*)(vb + (size_t)r * DM + lc);
            *(float4*)&Vs[r][lc] = vv;
        }
        __syncthreads();

        // scores s[i][j] = sum_dh Q[row_i][dh] * K[col_j][dh]
        float s[4][4];
#pragma unroll
        for (int i = 0; i < 4; i++)
#pragma unroll
            for (int j = 0; j < 4; j++) s[i][j] = 0.0f;

#pragma unroll 16
        for (int kk = 0; kk < 64; kk++) {
            float4 a  = *(const float4*)&Qs[kk][ty * 4];
            float4 bv = *(const float4*)&KP[kk][tx * 4];
            float ar[4] = {a.x, a.y, a.z, a.w};
            float br[4] = {bv.x, bv.y, bv.z, bv.w};
#pragma unroll
            for (int i = 0; i < 4; i++)
#pragma unroll
                for (int j = 0; j < 4; j++) s[i][j] += ar[i] * br[j];
        }

        const float sc = 0.125f;  // 1/sqrt(64)
        const bool diag = (kt == qt);
#pragma unroll
        for (int i = 0; i < 4; i++)
#pragma unroll
            for (int j = 0; j < 4; j++) {
                float v = s[i][j] * sc;
                if (diag && (tx * 4 + j > ty * 4 + i)) v = -1e30f;
                s[i][j] = v;
            }

        // online softmax update
        float p4[4][4];
#pragma unroll
        for (int i = 0; i < 4; i++) {
            float rm = fmaxf(fmaxf(s[i][0], s[i][1]), fmaxf(s[i][2], s[i][3]));
#pragma unroll
            for (int o = 8; o > 0; o >>= 1)
                rm = fmaxf(rm, __shfl_xor_sync(0xffffffffu, rm, o, 16));
            float nm   = fmaxf(m_i[i], rm);
            float corr = __expf(m_i[i] - nm);
            float rs = 0.0f;
#pragma unroll
            for (int j = 0; j < 4; j++) {
                float e = __expf(s[i][j] - nm);
                p4[i][j] = e;
                rs += e;
            }
#pragma unroll
            for (int o = 8; o > 0; o >>= 1)
                rs += __shfl_xor_sync(0xffffffffu, rs, o, 16);
            l_i[i] = l_i[i] * corr + rs;
            m_i[i] = nm;
#pragma unroll
            for (int j = 0; j < 4; j++) acc[i][j] *= corr;
        }

        __syncthreads();  // everyone done reading KP as K
#pragma unroll
        for (int i = 0; i < 4; i++)
            *(float4*)&KP[ty * 4 + i][tx * 4] =
                make_float4(p4[i][0], p4[i][1], p4[i][2], p4[i][3]);
        __syncthreads();

        // acc[i][d] += sum_j P[row_i][j] * V[j][d]
#pragma unroll 4
        for (int jj = 0; jj < 64; jj += 4) {
            float4 v0 = *(const float4*)&Vs[jj + 0][tx * 4];
            float4 v1 = *(const float4*)&Vs[jj + 1][tx * 4];
            float4 v2 = *(const float4*)&Vs[jj + 2][tx * 4];
            float4 v3 = *(const float4*)&Vs[jj + 3][tx * 4];
#pragma unroll
            for (int i = 0; i < 4; i++) {
                float4 pv = *(const float4*)&KP[ty * 4 + i][jj];
                acc[i][0] += pv.x * v0.x + pv.y * v1.x + pv.z * v2.x + pv.w * v3.x;
                acc[i][1] += pv.x * v0.y + pv.y * v1.y + pv.z * v2.y + pv.w * v3.y;
                acc[i][2] += pv.x * v0.z + pv.y * v1.z + pv.z * v2.z + pv.w * v3.z;
                acc[i][3] += pv.x * v0.w + pv.y * v1.w + pv.z * v2.w + pv.w * v3.w;
            }
        }
        __syncthreads();
    }

    float* ob = O + ((size_t)(b * SQ + qt * 64)) * DM + h * HD;
#pragma unroll
    for (int i = 0; i < 4; i++) {
        float inv = 1.0f / l_i[i];
        *(float4*)(ob + (size_t)(ty * 4 + i) * DM + tx * 4) =
            make_float4(acc[i][0] * inv, acc[i][1] * inv,
                        acc[i][2] * inv, acc[i][3] * inv);
    }
}

// ---------------------------------------------------------------------------
extern "C" void kernel_launch(void* const* d_in, const int* in_sizes, int n_in,
                              void* d_out, int out_size) {
    const float* wq = (const float*)d_in[0];
    const float* wk = (const float*)d_in[1];
    const float* wv = (const float*)d_in[2];
    const float* wo = (const float*)d_in[3];
    const float* x  = (const float*)d_in[4];
    float* out = (float*)d_out;

    float *q, *k, *v, *a;
    cudaGetSymbolAddress((void**)&q, g_q);
    cudaGetSymbolAddress((void**)&k, g_k);
    cudaGetSymbolAddress((void**)&v, g_v);
    cudaGetSymbolAddress((void**)&a, g_attn);

    dim3 gg(DM / 128, MT / 128);  // (8, 32)
    gemm_nt<<<gg, 256>>>(x, wq, q);
    gemm_nt<<<gg, 256>>>(x, wk, k);
    gemm_nt<<<gg, 256>>>(x, wv, v);
    attn_kernel<<<dim3(SQ / 64, NH, BB), 256>>>(q, k, v, a);
    gemm_nt<<<gg, 256>>>(a, wo, out);
}

// round 4
// speedup vs baseline: 1.6944x; 1.6944x over previous
#include <cuda_runtime.h>
#include <cstdint>
#include <cstddef>

// Problem constants
constexpr int DM = 1024;   // d_model
constexpr int SQ = 2048;   // seq len
constexpr int BB = 2;      // batch
constexpr int NH = 16;     // heads
constexpr int HD = 64;     // head dim
constexpr int MT = BB * SQ; // 4096 total rows

// Scratch (static device globals — no cudaMalloc allowed)
__device__ float g_q[MT * DM];
__device__ float g_k[MT * DM];
__device__ float g_v[MT * DM];
__device__ float g_attn[MT * DM];
__device__ float g_xc[MT * DM];        // tf32-rounded input activations
__device__ float g_wc[4][DM * DM];     // tf32-rounded weights (q,k,v,o)

// ---------------------------------------------------------------------------
// tf32 helpers
// ---------------------------------------------------------------------------
__device__ __forceinline__ uint32_t f2tf32(float x) {
    uint32_t r;
    asm("cvt.rna.tf32.f32 %0, %1;" : "=r"(r) : "f"(x));
    return r;
}

__device__ __forceinline__ void mma_tf32(float c[4],
                                         uint32_t a0, uint32_t a1, uint32_t a2, uint32_t a3,
                                         uint32_t b0, uint32_t b1) {
    asm volatile(
        "mma.sync.aligned.m16n8k8.row.col.f32.tf32.tf32.f32 "
        "{%0,%1,%2,%3}, {%4,%5,%6,%7}, {%8,%9}, {%0,%1,%2,%3};\n"
        : "+f"(c[0]), "+f"(c[1]), "+f"(c[2]), "+f"(c[3])
        : "r"(a0), "r"(a1), "r"(a2), "r"(a3), "r"(b0), "r"(b1));
}

#define CP_ASYNC16(dst, src) \
    asm volatile("cp.async.cg.shared.global [%0], [%1], 16;\n" :: "r"(dst), "l"(src))
#define CP_COMMIT() asm volatile("cp.async.commit_group;\n" ::)

// ---------------------------------------------------------------------------
// Pre-pass: round fp32 -> tf32 (rna) so the GEMM hot loop needs no cvt.
// ---------------------------------------------------------------------------
__global__ void cvt_rna_kernel(const float4* __restrict__ src,
                               float4* __restrict__ dst, int n4) {
    int i = blockIdx.x * 256 + threadIdx.x;
    if (i < n4) {
        float4 v = src[i];
        float4 o;
        o.x = __uint_as_float(f2tf32(v.x));
        o.y = __uint_as_float(f2tf32(v.y));
        o.z = __uint_as_float(f2tf32(v.z));
        o.w = __uint_as_float(f2tf32(v.w));
        dst[i] = o;
    }
}

// ---------------------------------------------------------------------------
// C[m][n] = sum_k A[m][k] * W[n][k], A/W pre-rounded to tf32.
// 128x128 tile, BK=32, 256 threads = 8 warps (2x4), warp tile 64x32,
// m16n8k8 tf32 mma. cp.async double-buffered smem, XOR-swizzled (conflict-free).
// Dynamic smem: 2 bufs x (A 16KB + B 16KB) = 64KB.
// ---------------------------------------------------------------------------
__device__ __forceinline__ void gemm_body(const float* __restrict__ A,
                                          const float* __restrict__ W,
                                          float* __restrict__ C,
                                          int m0, int n0) {
    constexpr int K = DM, N = DM;
    extern __shared__ uint32_t sm[];   // [2][A 4096 words | B 4096 words]

    const int tid  = threadIdx.x;
    const int lane = tid & 31;
    const int wid  = tid >> 5;
    const int g    = lane >> 2;   // groupID 0..7
    const int t    = lane & 3;    // threadID_in_group 0..3
    const int wm   = wid >> 2;    // 0..1  -> rows wm*64
    const int wn   = wid & 3;     // 0..3  -> cols wn*32

    const int f  = tid & 7;       // float4 slot within a 32-float row
    const int r0 = tid >> 3;      // 0..31

    const uint32_t smem_base = (uint32_t)__cvta_generic_to_shared(sm);

    float c[4][4][4];
#pragma unroll
    for (int mi = 0; mi < 4; mi++)
#pragma unroll
        for (int ni = 0; ni < 4; ni++)
#pragma unroll
            for (int e = 0; e < 4; e++) c[mi][ni][e] = 0.0f;

    // ---- tile prefetch ----
    auto issue_tile = [&](int j, int buf) {
        uint32_t base = smem_base + buf * (8192u * 4u);
#pragma unroll
        for (int p = 0; p < 4; p++) {
            int r = r0 + p * 32;
            uint32_t off = (uint32_t)(r * 32 + ((f ^ (r & 7)) << 2)) * 4u;
            CP_ASYNC16(base + off,
                       A + (size_t)(m0 + r) * K + j * 32 + f * 4);
            CP_ASYNC16(base + 16384u + off,
                       W + (size_t)(n0 + r) * K + j * 32 + f * 4);
        }
        CP_COMMIT();
    };

    issue_tile(0, 0);

    constexpr int NIT = K / 32;  // 32
    for (int it = 0; it < NIT; ++it) {
        if (it + 1 < NIT) {
            issue_tile(it + 1, (it + 1) & 1);
            asm volatile("cp.async.wait_group 1;\n" ::);
        } else {
            asm volatile("cp.async.wait_group 0;\n" ::);
        }
        __syncthreads();

        const uint32_t* As = sm + (it & 1) * 8192;
        const uint32_t* Bs = As + 4096;

#pragma unroll
        for (int k4 = 0; k4 < 8; k4 += 2) {   // k-step of 8 (two float4 slots)
            uint32_t af[4][4];
#pragma unroll
            for (int mi = 0; mi < 4; mi++) {
                int r1 = wm * 64 + mi * 16 + g;
                int r2 = r1 + 8;
                int s0 = (k4 ^ g) << 2;        // r1&7 == r2&7 == g
                int s1 = ((k4 + 1) ^ g) << 2;
                af[mi][0] = As[r1 * 32 + s0 + t];
                af[mi][1] = As[r2 * 32 + s0 + t];
                af[mi][2] = As[r1 * 32 + s1 + t];
                af[mi][3] = As[r2 * 32 + s1 + t];
            }
            uint32_t bf[4][2];
#pragma unroll
            for (int ni = 0; ni < 4; ni++) {
                int rn = wn * 32 + ni * 8 + g;
                int s0 = (k4 ^ g) << 2;
                int s1 = ((k4 + 1) ^ g) << 2;
                bf[ni][0] = Bs[rn * 32 + s0 + t];
                bf[ni][1] = Bs[rn * 32 + s1 + t];
            }
#pragma unroll
            for (int mi = 0; mi < 4; mi++)
#pragma unroll
                for (int ni = 0; ni < 4; ni++)
                    mma_tf32(c[mi][ni],
                             af[mi][0], af[mi][1], af[mi][2], af[mi][3],
                             bf[ni][0], bf[ni][1]);
        }
        __syncthreads();
    }

    // ---- writeback ----
#pragma unroll
    for (int mi = 0; mi < 4; mi++) {
        int row = m0 + wm * 64 + mi * 16 + g;
#pragma unroll
        for (int ni = 0; ni < 4; ni++) {
            int col = n0 + wn * 32 + ni * 8 + 2 * t;
            *(float2*)(C + (size_t)row * N + col) =
                make_float2(c[mi][ni][0], c[mi][ni][1]);
            *(float2*)(C + (size_t)(row + 8) * N + col) =
                make_float2(c[mi][ni][2], c[mi][ni][3]);
        }
    }
}

__global__ __launch_bounds__(256) void gemm_tf32(const float* __restrict__ A,
                                                 const float* __restrict__ W,
                                                 float* __restrict__ C) {
    gemm_body(A, W, C, blockIdx.y * 128, blockIdx.x * 128);
}

// Fused QKV: blockIdx.z selects weight/output (768 CTAs -> better wave packing)
__global__ __launch_bounds__(256) void gemm_qkv(const float* __restrict__ X,
                                                const float* __restrict__ Wq,
                                                const float* __restrict__ Wk,
                                                const float* __restrict__ Wv,
                                                float* __restrict__ Q,
                                                float* __restrict__ Ko,
                                                float* __restrict__ V) {
    const float* W = (blockIdx.z == 0) ? Wq : (blockIdx.z == 1 ? Wk : Wv);
    float*       C = (blockIdx.z == 0) ? Q  : (blockIdx.z == 1 ? Ko : V);
    gemm_body(X, W, C, blockIdx.y * 128, blockIdx.x * 128);
}

// ---------------------------------------------------------------------------
// Flash-style causal attention (unchanged math). Heavy q-tiles scheduled first
// (reversed blockIdx.x). Epilogue rounds output to tf32 for the o-proj GEMM.
// ---------------------------------------------------------------------------
__global__ __launch_bounds__(256) void attn_kernel(const float* __restrict__ Q,
                                                   const float* __restrict__ Kg,
                                                   const float* __restrict__ V,
                                                   float* __restrict__ O) {
    __shared__ float Qs[64][64];
    __shared__ float KP[64][64];
    __shared__ float Vs[64][64];

    const int tid = threadIdx.x;
    const int ty = tid >> 4;
    const int tx = tid & 15;
    const int qt = (SQ / 64 - 1) - blockIdx.x;   // heavy tiles first
    const int h  = blockIdx.y;
    const int b  = blockIdx.z;

    const int lr = tid >> 4;
    const int lc = (tid & 15) * 4;

    const float* qb = Q + ((size_t)(b * SQ + qt * 64)) * DM + h * HD;

#pragma unroll
    for (int p = 0; p < 4; p++) {
        int r = lr + p * 16;
        float4 v = *(const float4*)(qb + (size_t)r * DM + lc);
        Qs[lc + 0][r] = v.x; Qs[lc + 1][r] = v.y;
        Qs[lc + 2][r] = v.z; Qs[lc + 3][r] = v.w;
    }

    float m_i[4], l_i[4], acc[4][4];
#pragma unroll
    for (int i = 0; i < 4; i++) {
        m_i[i] = -1e30f;
        l_i[i] = 0.0f;
#pragma unroll
        for (int j = 0; j < 4; j++) acc[i][j] = 0.0f;
    }
    __syncthreads();

    for (int kt = 0; kt <= qt; kt++) {
        const float* kb = Kg + ((size_t)(b * SQ + kt * 64)) * DM + h * HD;
        const float* vb = V  + ((size_t)(b * SQ + kt * 64)) * DM + h * HD;
#pragma unroll
        for (int p = 0; p < 4; p++) {
            int r = lr + p * 16;
            float4 kv = *(const float4*)(kb + (size_t)r * DM + lc);
            KP[lc + 0][r] = kv.x; KP[lc + 1][r] = kv.y;
            KP[lc + 2][r] = kv.z; KP[lc + 3][r] = kv.w;
            float4 vv = *(const float4*)(vb + (size_t)r * DM + lc);
            *(float4*)&Vs[r][lc] = vv;
        }
        __syncthreads();

        float s[4][4];
#pragma unroll
        for (int i = 0; i < 4; i++)
#pragma unroll
            for (int j = 0; j < 4; j++) s[i][j] = 0.0f;

#pragma unroll 16
        for (int kk = 0; kk < 64; kk++) {
            float4 a  = *(const float4*)&Qs[kk][ty * 4];
            float4 bv = *(const float4*)&KP[kk][tx * 4];
            float ar[4] = {a.x, a.y, a.z, a.w};
            float br[4] = {bv.x, bv.y, bv.z, bv.w};
#pragma unroll
            for (int i = 0; i < 4; i++)
#pragma unroll
                for (int j = 0; j < 4; j++) s[i][j] += ar[i] * br[j];
        }

        const float sc = 0.125f;
        const bool diag = (kt == qt);
#pragma unroll
        for (int i = 0; i < 4; i++)
#pragma unroll
            for (int j = 0; j < 4; j++) {
                float v = s[i][j] * sc;
                if (diag && (tx * 4 + j > ty * 4 + i)) v = -1e30f;
                s[i][j] = v;
            }

        float p4[4][4];
#pragma unroll
        for (int i = 0; i < 4; i++) {
            float rm = fmaxf(fmaxf(s[i][0], s[i][1]), fmaxf(s[i][2], s[i][3]));
#pragma unroll
            for (int o = 8; o > 0; o >>= 1)
                rm = fmaxf(rm, __shfl_xor_sync(0xffffffffu, rm, o, 16));
            float nm   = fmaxf(m_i[i], rm);
            float corr = __expf(m_i[i] - nm);
            float rs = 0.0f;
#pragma unroll
            for (int j = 0; j < 4; j++) {
                float e = __expf(s[i][j] - nm);
                p4[i][j] = e;
                rs += e;
            }
#pragma unroll
            for (int o = 8; o > 0; o >>= 1)
                rs += __shfl_xor_sync(0xffffffffu, rs, o, 16);
            l_i[i] = l_i[i] * corr + rs;
            m_i[i] = nm;
#pragma unroll
            for (int j = 0; j < 4; j++) acc[i][j] *= corr;
        }

        __syncthreads();
#pragma unroll
        for (int i = 0; i < 4; i++)
            *(float4*)&KP[ty * 4 + i][tx * 4] =
                make_float4(p4[i][0], p4[i][1], p4[i][2], p4[i][3]);
        __syncthreads();

#pragma unroll 4
        for (int jj = 0; jj < 64; jj += 4) {
            float4 v0 = *(const float4*)&Vs[jj + 0][tx * 4];
            float4 v1 = *(const float4*)&Vs[jj + 1][tx * 4];
            float4 v2 = *(const float4*)&Vs[jj + 2][tx * 4];
            float4 v3 = *(const float4*)&Vs[jj + 3][tx * 4];
#pragma unroll
            for (int i = 0; i < 4; i++) {
                float4 pv = *(const float4*)&KP[ty * 4 + i][jj];
                acc[i][0] += pv.x * v0.x + pv.y * v1.x + pv.z * v2.x + pv.w * v3.x;
                acc[i][1] += pv.x * v0.y + pv.y * v1.y + pv.z * v2.y + pv.w * v3.y;
                acc[i][2] += pv.x * v0.z + pv.y * v1.z + pv.z * v2.z + pv.w * v3.z;
                acc[i][3] += pv.x * v0.w + pv.y * v1.w + pv.z * v2.w + pv.w * v3.w;
            }
        }
        __syncthreads();
    }

    float* ob = O + ((size_t)(b * SQ + qt * 64)) * DM + h * HD;
#pragma unroll
    for (int i = 0; i < 4; i++) {
        float inv = 1.0f / l_i[i];
        float4 o;
        o.x = __uint_as_float(f2tf32(acc[i][0] * inv));
        o.y = __uint_as_float(f2tf32(acc[i][1] * inv));
        o.z = __uint_as_float(f2tf32(acc[i][2] * inv));
        o.w = __uint_as_float(f2tf32(acc[i][3] * inv));
        *(float4*)(ob + (size_t)(ty * 4 + i) * DM + tx * 4) = o;
    }
}

// ---------------------------------------------------------------------------
extern "C" void kernel_launch(void* const* d_in, const int* in_sizes, int n_in,
                              void* d_out, int out_size) {
    const float* wq = (const float*)d_in[0];
    const float* wk = (const float*)d_in[1];
    const float* wv = (const float*)d_in[2];
    const float* wo = (const float*)d_in[3];
    const float* x  = (const float*)d_in[4];
    float* out = (float*)d_out;

    float *q, *k, *v, *a, *xc, *wc;
    cudaGetSymbolAddress((void**)&q,  g_q);
    cudaGetSymbolAddress((void**)&k,  g_k);
    cudaGetSymbolAddress((void**)&v,  g_v);
    cudaGetSymbolAddress((void**)&a,  g_attn);
    cudaGetSymbolAddress((void**)&xc, g_xc);
    cudaGetSymbolAddress((void**)&wc, g_wc);
    float* wc0 = wc;
    float* wc1 = wc + DM * DM;
    float* wc2 = wc + 2 * DM * DM;
    float* wc3 = wc + 3 * DM * DM;

    // Idempotent, called every time (no static guards per harness rules)
    cudaFuncSetAttribute(gemm_tf32, cudaFuncAttributeMaxDynamicSharedMemorySize, 65536);
    cudaFuncSetAttribute(gemm_qkv,  cudaFuncAttributeMaxDynamicSharedMemorySize, 65536);

    // Pre-pass: tf32-round the GEMM operands
    int n4x = MT * DM / 4;
    int n4w = DM * DM / 4;
    cvt_rna_kernel<<<(n4x + 255) / 256, 256>>>((const float4*)x,  (float4*)xc,  n4x);
    cvt_rna_kernel<<<(n4w + 255) / 256, 256>>>((const float4*)wq, (float4*)wc0, n4w);
    cvt_rna_kernel<<<(n4w + 255) / 256, 256>>>((const float4*)wk, (float4*)wc1, n4w);
    cvt_rna_kernel<<<(n4w + 255) / 256, 256>>>((const float4*)wv, (float4*)wc2, n4w);
    cvt_rna_kernel<<<(n4w + 255) / 256, 256>>>((const float4*)wo, (float4*)wc3, n4w);

    dim3 gq(DM / 128, MT / 128, 3);   // fused QKV
    gemm_qkv<<<gq, 256, 65536>>>(xc, wc0, wc1, wc2, q, k, v);

    attn_kernel<<<dim3(SQ / 64, NH, BB), 256>>>(q, k, v, a);

    dim3 gg(DM / 128, MT / 128);
    gemm_tf32<<<gg, 256, 65536>>>(a, wc3, out);
}

// round 12
// speedup vs baseline: 3.4328x; 2.0259x over previous
#include <cuda_runtime.h>
#include <cstdint>
#include <cstddef>

// Problem constants
constexpr int DM = 1024;   // d_model
constexpr int SQ = 2048;   // seq len
constexpr int BB = 2;      // batch
constexpr int NH = 16;     // heads
constexpr int HD = 64;     // head dim
constexpr int MT = BB * SQ; // 4096 total rows

// Scratch (static device globals — no cudaMalloc allowed)
__device__ float g_q[MT * DM];
__device__ float g_k[MT * DM];
__device__ float g_v[MT * DM];
__device__ float g_attn[MT * DM];
__device__ float g_xc[MT * DM];        // tf32-rounded input activations
__device__ float g_wc[4][DM * DM];     // tf32-rounded weights (q,k,v,o)

// ---------------------------------------------------------------------------
// tf32 helpers
// ---------------------------------------------------------------------------
__device__ __forceinline__ uint32_t f2tf32(float x) {
    uint32_t r;
    asm("cvt.rna.tf32.f32 %0, %1;" : "=r"(r) : "f"(x));
    return r;
}
__device__ __forceinline__ float rna(float x) { return __uint_as_float(f2tf32(x)); }

__device__ __forceinline__ void mma_tf32(float c[4],
                                         uint32_t a0, uint32_t a1, uint32_t a2, uint32_t a3,
                                         uint32_t b0, uint32_t b1) {
    asm volatile(
        "mma.sync.aligned.m16n8k8.row.col.f32.tf32.tf32.f32 "
        "{%0,%1,%2,%3}, {%4,%5,%6,%7}, {%8,%9}, {%0,%1,%2,%3};\n"
        : "+f"(c[0]), "+f"(c[1]), "+f"(c[2]), "+f"(c[3])
        : "r"(a0), "r"(a1), "r"(a2), "r"(a3), "r"(b0), "r"(b1));
}

#define CP_ASYNC16(dst, src) \
    asm volatile("cp.async.cg.shared.global [%0], [%1], 16;\n" :: "r"(dst), "l"(src))
#define CP_COMMIT() asm volatile("cp.async.commit_group;\n" ::)

// ---------------------------------------------------------------------------
// Pre-pass: round fp32 -> tf32 (rna)
// ---------------------------------------------------------------------------
__global__ void cvt_rna_kernel(const float4* __restrict__ src,
                               float4* __restrict__ dst, int n4) {
    int i = blockIdx.x * 256 + threadIdx.x;
    if (i < n4) {
        float4 v = src[i];
        float4 o;
        o.x = rna(v.x); o.y = rna(v.y); o.z = rna(v.z); o.w = rna(v.w);
        dst[i] = o;
    }
}

// ---------------------------------------------------------------------------
// GEMM: C[m][n] = sum_k A[m][k] * W[n][k]  (tf32 HMMA, measured ~143 TF/s)
// ---------------------------------------------------------------------------
__device__ __forceinline__ void gemm_body(const float* __restrict__ A,
                                          const float* __restrict__ W,
                                          float* __restrict__ C,
                                          int m0, int n0) {
    constexpr int K = DM, N = DM;
    extern __shared__ uint32_t sm[];

    const int tid  = threadIdx.x;
    const int lane = tid & 31;
    const int wid  = tid >> 5;
    const int g    = lane >> 2;
    const int t    = lane & 3;
    const int wm   = wid >> 2;
    const int wn   = wid & 3;

    const int f  = tid & 7;
    const int r0 = tid >> 3;

    const uint32_t smem_base = (uint32_t)__cvta_generic_to_shared(sm);

    float c[4][4][4];
#pragma unroll
    for (int mi = 0; mi < 4; mi++)
#pragma unroll
        for (int ni = 0; ni < 4; ni++)
#pragma unroll
            for (int e = 0; e < 4; e++) c[mi][ni][e] = 0.0f;

    auto issue_tile = [&](int j, int buf) {
        uint32_t base = smem_base + buf * (8192u * 4u);
#pragma unroll
        for (int p = 0; p < 4; p++) {
            int r = r0 + p * 32;
            uint32_t off = (uint32_t)(r * 32 + ((f ^ (r & 7)) << 2)) * 4u;
            CP_ASYNC16(base + off,           A + (size_t)(m0 + r) * K + j * 32 + f * 4);
            CP_ASYNC16(base + 16384u + off,  W + (size_t)(n0 + r) * K + j * 32 + f * 4);
        }
        CP_COMMIT();
    };

    issue_tile(0, 0);

    constexpr int NIT = K / 32;
    for (int it = 0; it < NIT; ++it) {
        if (it + 1 < NIT) {
            issue_tile(it + 1, (it + 1) & 1);
            asm volatile("cp.async.wait_group 1;\n" ::);
        } else {
            asm volatile("cp.async.wait_group 0;\n" ::);
        }
        __syncthreads();

        const uint32_t* As = sm + (it & 1) * 8192;
        const uint32_t* Bs = As + 4096;

#pragma unroll
        for (int k4 = 0; k4 < 8; k4 += 2) {
            uint32_t af[4][4];
#pragma unroll
            for (int mi = 0; mi < 4; mi++) {
                int r1 = wm * 64 + mi * 16 + g;
                int r2 = r1 + 8;
                int s0 = (k4 ^ g) << 2;
                int s1 = ((k4 + 1) ^ g) << 2;
                af[mi][0] = As[r1 * 32 + s0 + t];
                af[mi][1] = As[r2 * 32 + s0 + t];
                af[mi][2] = As[r1 * 32 + s1 + t];
                af[mi][3] = As[r2 * 32 + s1 + t];
            }
            uint32_t bf[4][2];
#pragma unroll
            for (int ni = 0; ni < 4; ni++) {
                int rn = wn * 32 + ni * 8 + g;
                int s0 = (k4 ^ g) << 2;
                int s1 = ((k4 + 1) ^ g) << 2;
                bf[ni][0] = Bs[rn * 32 + s0 + t];
                bf[ni][1] = Bs[rn * 32 + s1 + t];
            }
#pragma unroll
            for (int mi = 0; mi < 4; mi++)
#pragma unroll
                for (int ni = 0; ni < 4; ni++)
                    mma_tf32(c[mi][ni],
                             af[mi][0], af[mi][1], af[mi][2], af[mi][3],
                             bf[ni][0], bf[ni][1]);
        }
        __syncthreads();
    }

#pragma unroll
    for (int mi = 0; mi < 4; mi++) {
        int row = m0 + wm * 64 + mi * 16 + g;
#pragma unroll
        for (int ni = 0; ni < 4; ni++) {
            int col = n0 + wn * 32 + ni * 8 + 2 * t;
            *(float2*)(C + (size_t)row * N + col) =
                make_float2(c[mi][ni][0], c[mi][ni][1]);
            *(float2*)(C + (size_t)(row + 8) * N + col) =
                make_float2(c[mi][ni][2], c[mi][ni][3]);
        }
    }
}

__global__ __launch_bounds__(256) void gemm_tf32(const float* __restrict__ A,
                                                 const float* __restrict__ W,
                                                 float* __restrict__ C) {
    gemm_body(A, W, C, blockIdx.y * 128, blockIdx.x * 128);
}

__global__ __launch_bounds__(256) void gemm_qkv(const float* __restrict__ X,
                                                const float* __restrict__ Wq,
                                                const float* __restrict__ Wk,
                                                const float* __restrict__ Wv,
                                                float* __restrict__ Q,
                                                float* __restrict__ Ko,
                                                float* __restrict__ V) {
    const float* W = (blockIdx.z == 0) ? Wq : (blockIdx.z == 1 ? Wk : Wv);
    float*       C = (blockIdx.z == 0) ? Q  : (blockIdx.z == 1 ? Ko : V);
    gemm_body(X, W, C, blockIdx.y * 128, blockIdx.x * 128);
}

// ---------------------------------------------------------------------------
// Tensor-core flash attention.
// CTA: 128 q-rows x (one head, one batch). 8 warps, 16 q-rows per warp.
// 64-key blocks, m16n8k8 tf32 for QK^T and PV. C->A fragment conversion via
// shuffles (no P smem round-trip). Padded-68 smem rows: conflict-free LDS.
// Dynamic smem: Qs[128][68] + Ks[64][68] + Vt[64][68] = 69632 B.
// ---------------------------------------------------------------------------
constexpr int PAD = 68;
constexpr int ATTN_SMEM = (128 * PAD + 64 * PAD + 64 * PAD) * 4;

__global__ __launch_bounds__(256) void attn_mma(const float* __restrict__ Q,
                                                const float* __restrict__ Kg,
                                                const float* __restrict__ V,
                                                float* __restrict__ O) {
    extern __shared__ float smf[];
    float* Qs = smf;                   // [128][PAD]
    float* Ks = smf + 128 * PAD;       // [64][PAD]  (row = key, col = dh)
    float* Vt = Ks + 64 * PAD;         // [64][PAD]  (row = dh,  col = key)

    const int tid  = threadIdx.x;
    const int lane = tid & 31;
    const int w    = tid >> 5;       // warp 0..7 -> q-rows w*16..w*16+15
    const int g    = lane >> 2;      // 0..7
    const int t    = lane & 3;       // 0..3

    const int qi = (SQ / 128 - 1) - blockIdx.x;   // heavy tiles first
    const int h  = blockIdx.y;
    const int b  = blockIdx.z;
    const int q0 = qi * 128;

    // ---- load Q tile (rounded to tf32) ----
    {
        const float* qb = Q + ((size_t)(b * SQ + q0)) * DM + h * HD;
        int r = tid >> 4, cw = (tid & 15) * 4;
#pragma unroll
        for (int p = 0; p < 8; p++) {
            int rr = r + p * 16;
            float4 v = *(const float4*)(qb + (size_t)rr * DM + cw);
            float4 o; o.x = rna(v.x); o.y = rna(v.y); o.z = rna(v.z); o.w = rna(v.w);
            *(float4*)&Qs[rr * PAD + cw] = o;
        }
    }

    float of[8][4];                 // O accum: n-tile over dh, C-layout
    float m_r[2] = {-1e30f, -1e30f};
    float l_r[2] = {0.0f, 0.0f};
#pragma unroll
    for (int n = 0; n < 8; n++)
#pragma unroll
        for (int e = 0; e < 4; e++) of[n][e] = 0.0f;

    const int rowA = q0 + w * 16 + g;
    const int rowB = rowA + 8;
    const int nkt  = 2 * qi + 2;

    for (int kt = 0; kt < nkt; kt++) {
        __syncthreads();   // previous block fully consumed
        // ---- load K block (rounded), V block transposed (rounded) ----
        {
            const float* kb = Kg + ((size_t)(b * SQ + kt * 64)) * DM + h * HD;
            const float* vb = V  + ((size_t)(b * SQ + kt * 64)) * DM + h * HD;
            int r = tid >> 4, cw = (tid & 15) * 4;
#pragma unroll
            for (int p = 0; p < 4; p++) {
                int rr = r + p * 16;
                float4 kv = *(const float4*)(kb + (size_t)rr * DM + cw);
                float4 o; o.x = rna(kv.x); o.y = rna(kv.y); o.z = rna(kv.z); o.w = rna(kv.w);
                *(float4*)&Ks[rr * PAD + cw] = o;
                float4 vv = *(const float4*)(vb + (size_t)rr * DM + cw);
                Vt[(cw + 0) * PAD + rr] = rna(vv.x);
                Vt[(cw + 1) * PAD + rr] = rna(vv.y);
                Vt[(cw + 2) * PAD + rr] = rna(vv.z);
                Vt[(cw + 3) * PAD + rr] = rna(vv.w);
            }
        }
        __syncthreads();

        const bool diag = (kt >= 2 * qi);
        // warp fully above diagonal in this key block -> skip compute
        if (kt * 64 > q0 + w * 16 + 15) continue;

        // ---- S = Q K^T (m16n8k8 over 8 k-chunks x 8 n-tiles) ----
        float s[8][4];
#pragma unroll
        for (int n = 0; n < 8; n++)
#pragma unroll
            for (int e = 0; e < 4; e++) s[n][e] = 0.0f;

#pragma unroll
        for (int kc = 0; kc < 8; kc++) {
            const float* qrow = &Qs[(w * 16 + g) * PAD + kc * 8];
            uint32_t a0 = __float_as_uint(qrow[t]);
            uint32_t a1 = __float_as_uint(qrow[8 * PAD + t]);
            uint32_t a2 = __float_as_uint(qrow[4 + t]);
            uint32_t a3 = __float_as_uint(qrow[8 * PAD + 4 + t]);
#pragma unroll
            for (int n = 0; n < 8; n++) {
                const float* krow = &Ks[(n * 8 + g) * PAD + kc * 8];
                uint32_t b0 = __float_as_uint(krow[t]);
                uint32_t b1 = __float_as_uint(krow[4 + t]);
                mma_tf32(s[n], a0, a1, a2, a3, b0, b1);
            }
        }

        // ---- scale + causal mask ----
        const float sc = 0.125f;
#pragma unroll
        for (int n = 0; n < 8; n++) {
            int c0 = kt * 64 + n * 8 + 2 * t;
            s[n][0] *= sc; s[n][1] *= sc; s[n][2] *= sc; s[n][3] *= sc;
            if (diag) {
                if (c0     > rowA) s[n][0] = -1e30f;
                if (c0 + 1 > rowA) s[n][1] = -1e30f;
                if (c0     > rowB) s[n][2] = -1e30f;
                if (c0 + 1 > rowB) s[n][3] = -1e30f;
            }
        }

        // ---- online softmax (rows A=g, B=g+8; reduce over 4-lane groups) ----
        float mA = -1e30f, mB = -1e30f;
#pragma unroll
        for (int n = 0; n < 8; n++) {
            mA = fmaxf(mA, fmaxf(s[n][0], s[n][1]));
            mB = fmaxf(mB, fmaxf(s[n][2], s[n][3]));
        }
        mA = fmaxf(mA, __shfl_xor_sync(0xffffffffu, mA, 1));
        mA = fmaxf(mA, __shfl_xor_sync(0xffffffffu, mA, 2));
        mB = fmaxf(mB, __shfl_xor_sync(0xffffffffu, mB, 1));
        mB = fmaxf(mB, __shfl_xor_sync(0xffffffffu, mB, 2));

        float nmA = fmaxf(m_r[0], mA), nmB = fmaxf(m_r[1], mB);
        float corrA = __expf(m_r[0] - nmA), corrB = __expf(m_r[1] - nmB);
        float sumA = 0.0f, sumB = 0.0f;
#pragma unroll
        for (int n = 0; n < 8; n++) {
            s[n][0] = __expf(s[n][0] - nmA);
            s[n][1] = __expf(s[n][1] - nmA);
            s[n][2] = __expf(s[n][2] - nmB);
            s[n][3] = __expf(s[n][3] - nmB);
            sumA += s[n][0] + s[n][1];
            sumB += s[n][2] + s[n][3];
        }
        sumA += __shfl_xor_sync(0xffffffffu, sumA, 1);
        sumA += __shfl_xor_sync(0xffffffffu, sumA, 2);
        sumB += __shfl_xor_sync(0xffffffffu, sumB, 1);
        sumB += __shfl_xor_sync(0xffffffffu, sumB, 2);
        l_r[0] = l_r[0] * corrA + sumA;
        l_r[1] = l_r[1] * corrB + sumB;
        m_r[0] = nmA; m_r[1] = nmB;
#pragma unroll
        for (int n = 0; n < 8; n++) {
            of[n][0] *= corrA; of[n][1] *= corrA;
            of[n][2] *= corrB; of[n][3] *= corrB;
        }

        // ---- round P to tf32 ----
#pragma unroll
        for (int n = 0; n < 8; n++) {
            s[n][0] = rna(s[n][0]); s[n][1] = rna(s[n][1]);
            s[n][2] = rna(s[n][2]); s[n][3] = rna(s[n][3]);
        }

        // ---- O += P V : A-frag from C-frag via shuffles ----
        const int sl0 = (lane & ~3) | (t >> 1);
        const int sl1 = sl0 + 2;
        const bool odd = (t & 1);
#pragma unroll
        for (int kc = 0; kc < 8; kc++) {
            float v00 = __shfl_sync(0xffffffffu, s[kc][0], sl0);
            float v01 = __shfl_sync(0xffffffffu, s[kc][1], sl0);
            float v10 = __shfl_sync(0xffffffffu, s[kc][0], sl1);
            float v11 = __shfl_sync(0xffffffffu, s[kc][1], sl1);
            float w00 = __shfl_sync(0xffffffffu, s[kc][2], sl0);
            float w01 = __shfl_sync(0xffffffffu, s[kc][3], sl0);
            float w10 = __shfl_sync(0xffffffffu, s[kc][2], sl1);
            float w11 = __shfl_sync(0xffffffffu, s[kc][3], sl1);
            uint32_t a0 = __float_as_uint(odd ? v01 : v00);
            uint32_t a2 = __float_as_uint(odd ? v11 : v10);
            uint32_t a1 = __float_as_uint(odd ? w01 : w00);
            uint32_t a3 = __float_as_uint(odd ? w11 : w10);
#pragma unroll
            for (int n = 0; n < 8; n++) {
                const float* vrow = &Vt[(n * 8 + g) * PAD + kc * 8];
                uint32_t b0 = __float_as_uint(vrow[t]);
                uint32_t b1 = __float_as_uint(vrow[4 + t]);
                mma_tf32(of[n], a0, a1, a2, a3, b0, b1);
            }
        }
    }

    // ---- epilogue: normalize, round to tf32, store ----
    float invA = 1.0f / l_r[0];
    float invB = 1.0f / l_r[1];
    float* obA = O + ((size_t)(b * SQ + q0 + w * 16 + g)) * DM + h * HD;
    float* obB = obA + (size_t)8 * DM;
#pragma unroll
    for (int n = 0; n < 8; n++) {
        int c = n * 8 + 2 * t;
        *(float2*)(obA + c) = make_float2(rna(of[n][0] * invA), rna(of[n][1] * invA));
        *(float2*)(obB + c) = make_float2(rna(of[n][2] * invB), rna(of[n][3] * invB));
    }
}

// ---------------------------------------------------------------------------
extern "C" void kernel_launch(void* const* d_in, const int* in_sizes, int n_in,
                              void* d_out, int out_size) {
    const float* wq = (const float*)d_in[0];
    const float* wk = (const float*)d_in[1];
    const float* wv = (const float*)d_in[2];
    const float* wo = (const float*)d_in[3];
    const float* x  = (const float*)d_in[4];
    float* out = (float*)d_out;

    float *q, *k, *v, *a, *xc, *wc;
    cudaGetSymbolAddress((void**)&q,  g_q);
    cudaGetSymbolAddress((void**)&k,  g_k);
    cudaGetSymbolAddress((void**)&v,  g_v);
    cudaGetSymbolAddress((void**)&a,  g_attn);
    cudaGetSymbolAddress((void**)&xc, g_xc);
    cudaGetSymbolAddress((void**)&wc, g_wc);
    float* wc0 = wc;
    float* wc1 = wc + DM * DM;
    float* wc2 = wc + 2 * DM * DM;
    float* wc3 = wc + 3 * DM * DM;

    cudaFuncSetAttribute(gemm_tf32, cudaFuncAttributeMaxDynamicSharedMemorySize, 65536);
    cudaFuncSetAttribute(gemm_qkv,  cudaFuncAttributeMaxDynamicSharedMemorySize, 65536);
    cudaFuncSetAttribute(attn_mma,  cudaFuncAttributeMaxDynamicSharedMemorySize, ATTN_SMEM);

    int n4x = MT * DM / 4;
    int n4w = DM * DM / 4;
    cvt_rna_kernel<<<(n4x + 255) / 256, 256>>>((const float4*)x,  (float4*)xc,  n4x);
    cvt_rna_kernel<<<(n4w + 255) / 256, 256>>>((const float4*)wq, (float4*)wc0, n4w);
    cvt_rna_kernel<<<(n4w + 255) / 256, 256>>>((const float4*)wk, (float4*)wc1, n4w);
    cvt_rna_kernel<<<(n4w + 255) / 256, 256>>>((const float4*)wv, (float4*)wc2, n4w);
    cvt_rna_kernel<<<(n4w + 255) / 256, 256>>>((const float4*)wo, (float4*)wc3, n4w);

    dim3 gq(DM / 128, MT / 128, 3);
    gemm_qkv<<<gq, 256, 65536>>>(xc, wc0, wc1, wc2, q, k, v);

    attn_mma<<<dim3(SQ / 128, NH, BB), 256, ATTN_SMEM>>>(q, k, v, a);

    dim3 gg(DM / 128, MT / 128);
    gemm_tf32<<<gg, 256, 65536>>>(a, wc3, out);
}

// round 16
// speedup vs baseline: 4.0252x; 1.1726x over previous
#include <cuda_runtime.h>
#include <cstdint>
#include <cstddef>

// Problem constants
constexpr int DM = 1024;   // d_model
constexpr int SQ = 2048;   // seq len
constexpr int BB = 2;      // batch
constexpr int NH = 16;     // heads
constexpr int HD = 64;     // head dim
constexpr int MT = BB * SQ; // 4096 total rows

// Scratch (static device globals — no cudaMalloc allowed)
__device__ float g_q[MT * DM];
__device__ float g_k[MT * DM];
__device__ float g_v[MT * DM];
__device__ float g_attn[MT * DM];
__device__ float g_xc[MT * DM];        // tf32-rounded input activations
__device__ float g_wc[4][DM * DM];     // tf32-rounded weights (q,k,v,o)

// ---------------------------------------------------------------------------
// tf32 helpers
// ---------------------------------------------------------------------------
__device__ __forceinline__ uint32_t f2tf32(float x) {
    uint32_t r;
    asm("cvt.rna.tf32.f32 %0, %1;" : "=r"(r) : "f"(x));
    return r;
}
__device__ __forceinline__ float rna(float x) { return __uint_as_float(f2tf32(x)); }

__device__ __forceinline__ void mma_tf32(float c[4],
                                         uint32_t a0, uint32_t a1, uint32_t a2, uint32_t a3,
                                         uint32_t b0, uint32_t b1) {
    asm volatile(
        "mma.sync.aligned.m16n8k8.row.col.f32.tf32.tf32.f32 "
        "{%0,%1,%2,%3}, {%4,%5,%6,%7}, {%8,%9}, {%0,%1,%2,%3};\n"
        : "+f"(c[0]), "+f"(c[1]), "+f"(c[2]), "+f"(c[3])
        : "r"(a0), "r"(a1), "r"(a2), "r"(a3), "r"(b0), "r"(b1));
}

#define CP_ASYNC16(dst, src) \
    asm volatile("cp.async.cg.shared.global [%0], [%1], 16;\n" :: "r"(dst), "l"(src))
#define CP_COMMIT() asm volatile("cp.async.commit_group;\n" ::)

// ---------------------------------------------------------------------------
// Pre-pass: round fp32 -> tf32 (rna). One kernel for x, one fused for 4 weights.
// ---------------------------------------------------------------------------
__global__ void cvt_rna_kernel(const float4* __restrict__ src,
                               float4* __restrict__ dst, int n4) {
    int i = blockIdx.x * 256 + threadIdx.x;
    if (i < n4) {
        float4 v = src[i];
        float4 o;
        o.x = rna(v.x); o.y = rna(v.y); o.z = rna(v.z); o.w = rna(v.w);
        dst[i] = o;
    }
}

__global__ void cvt_rna_w4(const float4* __restrict__ s0, const float4* __restrict__ s1,
                           const float4* __restrict__ s2, const float4* __restrict__ s3,
                           float4* __restrict__ d0, float4* __restrict__ d1,
                           float4* __restrict__ d2, float4* __restrict__ d3, int n4) {
    const float4* s = (blockIdx.y == 0) ? s0 : (blockIdx.y == 1) ? s1
                      : (blockIdx.y == 2) ? s2 : s3;
    float4* d = (blockIdx.y == 0) ? d0 : (blockIdx.y == 1) ? d1
                : (blockIdx.y == 2) ? d2 : d3;
    int i = blockIdx.x * 256 + threadIdx.x;
    if (i < n4) {
        float4 v = s[i];
        float4 o;
        o.x = rna(v.x); o.y = rna(v.y); o.z = rna(v.z); o.w = rna(v.w);
        d[i] = o;
    }
}

// ---------------------------------------------------------------------------
// GEMM: C[m][n] = sum_k A[m][k] * W[n][k]  (tf32 HMMA, measured ~143 TF/s)
// ROUND: apply rna to outputs (for Q/K/V feeding the tf32 attention).
// ---------------------------------------------------------------------------
template <bool ROUND>
__device__ __forceinline__ void gemm_body(const float* __restrict__ A,
                                          const float* __restrict__ W,
                                          float* __restrict__ C,
                                          int m0, int n0) {
    constexpr int K = DM, N = DM;
    extern __shared__ uint32_t sm[];

    const int tid  = threadIdx.x;
    const int lane = tid & 31;
    const int wid  = tid >> 5;
    const int g    = lane >> 2;
    const int t    = lane & 3;
    const int wm   = wid >> 2;
    const int wn   = wid & 3;

    const int f  = tid & 7;
    const int r0 = tid >> 3;

    const uint32_t smem_base = (uint32_t)__cvta_generic_to_shared(sm);

    float c[4][4][4];
#pragma unroll
    for (int mi = 0; mi < 4; mi++)
#pragma unroll
        for (int ni = 0; ni < 4; ni++)
#pragma unroll
            for (int e = 0; e < 4; e++) c[mi][ni][e] = 0.0f;

    auto issue_tile = [&](int j, int buf) {
        uint32_t base = smem_base + buf * (8192u * 4u);
#pragma unroll
        for (int p = 0; p < 4; p++) {
            int r = r0 + p * 32;
            uint32_t off = (uint32_t)(r * 32 + ((f ^ (r & 7)) << 2)) * 4u;
            CP_ASYNC16(base + off,           A + (size_t)(m0 + r) * K + j * 32 + f * 4);
            CP_ASYNC16(base + 16384u + off,  W + (size_t)(n0 + r) * K + j * 32 + f * 4);
        }
        CP_COMMIT();
    };

    issue_tile(0, 0);

    constexpr int NIT = K / 32;
    for (int it = 0; it < NIT; ++it) {
        if (it + 1 < NIT) {
            issue_tile(it + 1, (it + 1) & 1);
            asm volatile("cp.async.wait_group 1;\n" ::);
        } else {
            asm volatile("cp.async.wait_group 0;\n" ::);
        }
        __syncthreads();

        const uint32_t* As = sm + (it & 1) * 8192;
        const uint32_t* Bs = As + 4096;

#pragma unroll
        for (int k4 = 0; k4 < 8; k4 += 2) {
            uint32_t af[4][4];
#pragma unroll
            for (int mi = 0; mi < 4; mi++) {
                int r1 = wm * 64 + mi * 16 + g;
                int r2 = r1 + 8;
                int s0 = (k4 ^ g) << 2;
                int s1 = ((k4 + 1) ^ g) << 2;
                af[mi][0] = As[r1 * 32 + s0 + t];
                af[mi][1] = As[r2 * 32 + s0 + t];
                af[mi][2] = As[r1 * 32 + s1 + t];
                af[mi][3] = As[r2 * 32 + s1 + t];
            }
            uint32_t bf[4][2];
#pragma unroll
            for (int ni = 0; ni < 4; ni++) {
                int rn = wn * 32 + ni * 8 + g;
                int s0 = (k4 ^ g) << 2;
                int s1 = ((k4 + 1) ^ g) << 2;
                bf[ni][0] = Bs[rn * 32 + s0 + t];
                bf[ni][1] = Bs[rn * 32 + s1 + t];
            }
#pragma unroll
            for (int mi = 0; mi < 4; mi++)
#pragma unroll
                for (int ni = 0; ni < 4; ni++)
                    mma_tf32(c[mi][ni],
                             af[mi][0], af[mi][1], af[mi][2], af[mi][3],
                             bf[ni][0], bf[ni][1]);
        }
        __syncthreads();
    }

#pragma unroll
    for (int mi = 0; mi < 4; mi++) {
        int row = m0 + wm * 64 + mi * 16 + g;
#pragma unroll
        for (int ni = 0; ni < 4; ni++) {
            int col = n0 + wn * 32 + ni * 8 + 2 * t;
            float e0 = c[mi][ni][0], e1 = c[mi][ni][1];
            float e2 = c[mi][ni][2], e3 = c[mi][ni][3];
            if (ROUND) { e0 = rna(e0); e1 = rna(e1); e2 = rna(e2); e3 = rna(e3); }
            *(float2*)(C + (size_t)row * N + col)       = make_float2(e0, e1);
            *(float2*)(C + (size_t)(row + 8) * N + col) = make_float2(e2, e3);
        }
    }
}

__global__ __launch_bounds__(256) void gemm_tf32(const float* __restrict__ A,
                                                 const float* __restrict__ W,
                                                 float* __restrict__ C) {
    gemm_body<false>(A, W, C, blockIdx.y * 128, blockIdx.x * 128);
}

__global__ __launch_bounds__(256) void gemm_qkv(const float* __restrict__ X,
                                                const float* __restrict__ Wq,
                                                const float* __restrict__ Wk,
                                                const float* __restrict__ Wv,
                                                float* __restrict__ Q,
                                                float* __restrict__ Ko,
                                                float* __restrict__ V) {
    const float* W = (blockIdx.z == 0) ? Wq : (blockIdx.z == 1 ? Wk : Wv);
    float*       C = (blockIdx.z == 0) ? Q  : (blockIdx.z == 1 ? Ko : V);
    gemm_body<true>(X, W, C, blockIdx.y * 128, blockIdx.x * 128);
}

// ---------------------------------------------------------------------------
// Tensor-core flash attention, cp.async double-buffered K/V.
// Inputs Q/K/V are pre-rounded tf32 (QKV GEMM epilogue) -> raw cp.async loads.
// Q: [128][68] pad-68 (frag reads 4g+t: conflict-free).
// K: 2x[64][68] pad-68 (frag reads 4g+t: conflict-free).
// V: 2x[64][72] ROW-MAJOR pad-72 (72%32=8 -> PV B-frag reads 8t+g: conflict-free,
//    no transpose stores needed).
// Dynamic smem: (128*68 + 2*64*68 + 2*64*72)*4 = 106496 B -> 2 CTAs/SM.
// ---------------------------------------------------------------------------
constexpr int QPAD = 68;
constexpr int VPAD = 72;
constexpr int ATTN_SMEM = (128 * QPAD + 2 * 64 * QPAD + 2 * 64 * VPAD) * 4;

__global__ __launch_bounds__(256, 2) void attn_mma(const float* __restrict__ Q,
                                                   const float* __restrict__ Kg,
                                                   const float* __restrict__ V,
                                                   float* __restrict__ O) {
    extern __shared__ float smf[];
    float* Qs = smf;                              // [128][QPAD]
    float* Kb = smf + 128 * QPAD;                 // 2 x [64][QPAD]
    float* Vb = Kb + 2 * 64 * QPAD;               // 2 x [64][VPAD]
    const uint32_t smem_base = (uint32_t)__cvta_generic_to_shared(smf);
    const uint32_t kb_base   = smem_base + 128 * QPAD * 4;
    const uint32_t vb_base   = kb_base + 2 * 64 * QPAD * 4;

    const int tid  = threadIdx.x;
    const int lane = tid & 31;
    const int w    = tid >> 5;       // warp 0..7 -> q-rows w*16..w*16+15
    const int g    = lane >> 2;      // 0..7
    const int t    = lane & 3;       // 0..3

    const int qi = (SQ / 128 - 1) - blockIdx.x;   // heavy tiles first
    const int h  = blockIdx.y;
    const int b  = blockIdx.z;
    const int q0 = qi * 128;

    const int cr = tid >> 4;             // 0..15 copy row
    const int cc = (tid & 15) * 4;       // 0..60 copy col (float4)

    // ---- async copy of one K/V 64-row block into buffer `buf` ----
    auto issue_kv = [&](int kt, int buf) {
        const float* kb = Kg + ((size_t)(b * SQ + kt * 64)) * DM + h * HD;
        const float* vb = V  + ((size_t)(b * SQ + kt * 64)) * DM + h * HD;
        uint32_t kdst = kb_base + (uint32_t)buf * (64 * QPAD * 4);
        uint32_t vdst = vb_base + (uint32_t)buf * (64 * VPAD * 4);
#pragma unroll
        for (int p = 0; p < 4; p++) {
            int r = cr + p * 16;
            CP_ASYNC16(kdst + (uint32_t)(r * QPAD + cc) * 4, kb + (size_t)r * DM + cc);
            CP_ASYNC16(vdst + (uint32_t)(r * VPAD + cc) * 4, vb + (size_t)r * DM + cc);
        }
        CP_COMMIT();
    };

    // ---- prologue: Q tile + first two K/V blocks ----
    {
        const float* qb = Q + ((size_t)(b * SQ + q0)) * DM + h * HD;
#pragma unroll
        for (int p = 0; p < 8; p++) {
            int r = cr + p * 16;
            CP_ASYNC16(smem_base + (uint32_t)(r * QPAD + cc) * 4, qb + (size_t)r * DM + cc);
        }
    }
    const int nkt = 2 * qi + 2;
    issue_kv(0, 0);                 // commits Q + K0 + V0 as group 0
    if (nkt > 1) issue_kv(1, 1);    // group 1

    float of[8][4];
    float m_r[2] = {-1e30f, -1e30f};
    float l_r[2] = {0.0f, 0.0f};
#pragma unroll
    for (int n = 0; n < 8; n++)
#pragma unroll
        for (int e = 0; e < 4; e++) of[n][e] = 0.0f;

    const int rowA = q0 + w * 16 + g;
    const int rowB = rowA + 8;

    for (int kt = 0; kt < nkt; kt++) {
        if (kt + 1 < nkt) asm volatile("cp.async.wait_group 1;\n" ::);
        else              asm volatile("cp.async.wait_group 0;\n" ::);
        __syncthreads();

        const int buf = kt & 1;
        const float* Kc = Kb + buf * (64 * QPAD);
        const float* Vc = Vb + buf * (64 * VPAD);

        // warp fully above diagonal in this key block -> skip compute
        if (!(kt * 64 > q0 + w * 16 + 15)) {
            const bool diag = (kt >= 2 * qi);

            // ---- S = Q K^T ----
            float s[8][4];
#pragma unroll
            for (int n = 0; n < 8; n++)
#pragma unroll
                for (int e = 0; e < 4; e++) s[n][e] = 0.0f;

#pragma unroll
            for (int kc = 0; kc < 8; kc++) {
                const float* qrow = &Qs[(w * 16 + g) * QPAD + kc * 8];
                uint32_t a0 = __float_as_uint(qrow[t]);
                uint32_t a1 = __float_as_uint(qrow[8 * QPAD + t]);
                uint32_t a2 = __float_as_uint(qrow[4 + t]);
                uint32_t a3 = __float_as_uint(qrow[8 * QPAD + 4 + t]);
#pragma unroll
                for (int n = 0; n < 8; n++) {
                    const float* krow = &Kc[(n * 8 + g) * QPAD + kc * 8];
                    uint32_t b0 = __float_as_uint(krow[t]);
                    uint32_t b1 = __float_as_uint(krow[4 + t]);
                    mma_tf32(s[n], a0, a1, a2, a3, b0, b1);
                }
            }

            // ---- scale + causal mask ----
            const float sc = 0.125f;
#pragma unroll
            for (int n = 0; n < 8; n++) {
                int c0 = kt * 64 + n * 8 + 2 * t;
                s[n][0] *= sc; s[n][1] *= sc; s[n][2] *= sc; s[n][3] *= sc;
                if (diag) {
                    if (c0     > rowA) s[n][0] = -1e30f;
                    if (c0 + 1 > rowA) s[n][1] = -1e30f;
                    if (c0     > rowB) s[n][2] = -1e30f;
                    if (c0 + 1 > rowB) s[n][3] = -1e30f;
                }
            }

            // ---- online softmax ----
            float mA = -1e30f, mB = -1e30f;
#pragma unroll
            for (int n = 0; n < 8; n++) {
                mA = fmaxf(mA, fmaxf(s[n][0], s[n][1]));
                mB = fmaxf(mB, fmaxf(s[n][2], s[n][3]));
            }
            mA = fmaxf(mA, __shfl_xor_sync(0xffffffffu, mA, 1));
            mA = fmaxf(mA, __shfl_xor_sync(0xffffffffu, mA, 2));
            mB = fmaxf(mB, __shfl_xor_sync(0xffffffffu, mB, 1));
            mB = fmaxf(mB, __shfl_xor_sync(0xffffffffu, mB, 2));

            float nmA = fmaxf(m_r[0], mA), nmB = fmaxf(m_r[1], mB);
            float corrA = __expf(m_r[0] - nmA), corrB = __expf(m_r[1] - nmB);
            float sumA = 0.0f, sumB = 0.0f;
#pragma unroll
            for (int n = 0; n < 8; n++) {
                s[n][0] = __expf(s[n][0] - nmA);
                s[n][1] = __expf(s[n][1] - nmA);
                s[n][2] = __expf(s[n][2] - nmB);
                s[n][3] = __expf(s[n][3] - nmB);
                sumA += s[n][0] + s[n][1];
                sumB += s[n][2] + s[n][3];
            }
            sumA += __shfl_xor_sync(0xffffffffu, sumA, 1);
            sumA += __shfl_xor_sync(0xffffffffu, sumA, 2);
            sumB += __shfl_xor_sync(0xffffffffu, sumB, 1);
            sumB += __shfl_xor_sync(0xffffffffu, sumB, 2);
            l_r[0] = l_r[0] * corrA + sumA;
            l_r[1] = l_r[1] * corrB + sumB;
            m_r[0] = nmA; m_r[1] = nmB;
#pragma unroll
            for (int n = 0; n < 8; n++) {
                of[n][0] *= corrA; of[n][1] *= corrA;
                of[n][2] *= corrB; of[n][3] *= corrB;
            }

            // ---- round P to tf32 ----
#pragma unroll
            for (int n = 0; n < 8; n++) {
                s[n][0] = rna(s[n][0]); s[n][1] = rna(s[n][1]);
                s[n][2] = rna(s[n][2]); s[n][3] = rna(s[n][3]);
            }

            // ---- O += P V : A-frag via shuffles, B-frag from row-major V ----
            const int sl0 = (lane & ~3) | (t >> 1);
            const int sl1 = sl0 + 2;
            const bool odd = (t & 1);
#pragma unroll
            for (int kc = 0; kc < 8; kc++) {
                float v00 = __shfl_sync(0xffffffffu, s[kc][0], sl0);
                float v01 = __shfl_sync(0xffffffffu, s[kc][1], sl0);
                float v10 = __shfl_sync(0xffffffffu, s[kc][0], sl1);
                float v11 = __shfl_sync(0xffffffffu, s[kc][1], sl1);
                float w00 = __shfl_sync(0xffffffffu, s[kc][2], sl0);
                float w01 = __shfl_sync(0xffffffffu, s[kc][3], sl0);
                float w10 = __shfl_sync(0xffffffffu, s[kc][2], sl1);
                float w11 = __shfl_sync(0xffffffffu, s[kc][3], sl1);
                uint32_t a0 = __float_as_uint(odd ? v01 : v00);
                uint32_t a2 = __float_as_uint(odd ? v11 : v10);
                uint32_t a1 = __float_as_uint(odd ? w01 : w00);
                uint32_t a3 = __float_as_uint(odd ? w11 : w10);
                const float* vr0 = &Vc[(kc * 8 + t) * VPAD];
                const float* vr1 = &Vc[(kc * 8 + t + 4) * VPAD];
#pragma unroll
                for (int n = 0; n < 8; n++) {
                    uint32_t b0 = __float_as_uint(vr0[n * 8 + g]);
                    uint32_t b1 = __float_as_uint(vr1[n * 8 + g]);
                    mma_tf32(of[n], a0, a1, a2, a3, b0, b1);
                }
            }
        }

        __syncthreads();   // all reads of buf done before refilling it
        if (kt + 2 < nkt) issue_kv(kt + 2, buf);
    }

    // ---- epilogue: normalize, round to tf32 (feeds o-proj GEMM), store ----
    float invA = 1.0f / l_r[0];
    float invB = 1.0f / l_r[1];
    float* obA = O + ((size_t)(b * SQ + q0 + w * 16 + g)) * DM + h * HD;
    float* obB = obA + (size_t)8 * DM;
#pragma unroll
    for (int n = 0; n < 8; n++) {
        int c = n * 8 + 2 * t;
        *(float2*)(obA + c) = make_float2(rna(of[n][0] * invA), rna(of[n][1] * invA));
        *(float2*)(obB + c) = make_float2(rna(of[n][2] * invB), rna(of[n][3] * invB));
    }
}

// ---------------------------------------------------------------------------
extern "C" void kernel_launch(void* const* d_in, const int* in_sizes, int n_in,
                              void* d_out, int out_size) {
    const float* wq = (const float*)d_in[0];
    const float* wk = (const float*)d_in[1];
    const float* wv = (const float*)d_in[2];
    const float* wo = (const float*)d_in[3];
    const float* x  = (const float*)d_in[4];
    float* out = (float*)d_out;

    float *q, *k, *v, *a, *xc, *wc;
    cudaGetSymbolAddress((void**)&q,  g_q);
    cudaGetSymbolAddress((void**)&k,  g_k);
    cudaGetSymbolAddress((void**)&v,  g_v);
    cudaGetSymbolAddress((void**)&a,  g_attn);
    cudaGetSymbolAddress((void**)&xc, g_xc);
    cudaGetSymbolAddress((void**)&wc, g_wc);
    float* wc0 = wc;
    float* wc1 = wc + DM * DM;
    float* wc2 = wc + 2 * DM * DM;
    float* wc3 = wc + 3 * DM * DM;

    cudaFuncSetAttribute(gemm_tf32, cudaFuncAttributeMaxDynamicSharedMemorySize, 65536);
    cudaFuncSetAttribute(gemm_qkv,  cudaFuncAttributeMaxDynamicSharedMemorySize, 65536);
    cudaFuncSetAttribute(attn_mma,  cudaFuncAttributeMaxDynamicSharedMemorySize, ATTN_SMEM);

    int n4x = MT * DM / 4;
    int n4w = DM * DM / 4;
    cvt_rna_kernel<<<(n4x + 255) / 256, 256>>>((const float4*)x, (float4*)xc, n4x);
    cvt_rna_w4<<<dim3((n4w + 255) / 256, 4), 256>>>(
        (const float4*)wq, (const float4*)wk, (const float4*)wv, (const float4*)wo,
        (float4*)wc0, (float4*)wc1, (float4*)wc2, (float4*)wc3, n4w);

    dim3 gq(DM / 128, MT / 128, 3);
    gemm_qkv<<<gq, 256, 65536>>>(xc, wc0, wc1, wc2, q, k, v);

    attn_mma<<<dim3(SQ / 128, NH, BB), 256, ATTN_SMEM>>>(q, k, v, a);

    dim3 gg(DM / 128, MT / 128);
    gemm_tf32<<<gg, 256, 65536>>>(a, wc3, out);
}

// round 17
// speedup vs baseline: 4.1009x; 1.0188x over previous
#include <cuda_runtime.h>
#include <cstdint>
#include <cstddef>

// Problem constants
constexpr int DM = 1024;   // d_model
constexpr int SQ = 2048;   // seq len
constexpr int BB = 2;      // batch
constexpr int NH = 16;     // heads
constexpr int HD = 64;     // head dim
constexpr int MT = BB * SQ; // 4096 total rows

// Scratch (static device globals — no cudaMalloc allowed)
__device__ float g_q[MT * DM];
__device__ float g_k[MT * DM];
__device__ float g_v[MT * DM];
__device__ float g_attn[MT * DM];
__device__ float g_xc[MT * DM];        // tf32-rounded input activations
__device__ float g_wc[4][DM * DM];     // tf32-rounded weights (q,k,v,o)

// ---------------------------------------------------------------------------
// tf32 helpers
// ---------------------------------------------------------------------------
__device__ __forceinline__ uint32_t f2tf32(float x) {
    uint32_t r;
    asm("cvt.rna.tf32.f32 %0, %1;" : "=r"(r) : "f"(x));
    return r;
}
__device__ __forceinline__ float rna(float x) { return __uint_as_float(f2tf32(x)); }

__device__ __forceinline__ void mma_tf32(float c[4],
                                         uint32_t a0, uint32_t a1, uint32_t a2, uint32_t a3,
                                         uint32_t b0, uint32_t b1) {
    asm volatile(
        "mma.sync.aligned.m16n8k8.row.col.f32.tf32.tf32.f32 "
        "{%0,%1,%2,%3}, {%4,%5,%6,%7}, {%8,%9}, {%0,%1,%2,%3};\n"
        : "+f"(c[0]), "+f"(c[1]), "+f"(c[2]), "+f"(c[3])
        : "r"(a0), "r"(a1), "r"(a2), "r"(a3), "r"(b0), "r"(b1));
}

#define CP_ASYNC16(dst, src) \
    asm volatile("cp.async.cg.shared.global [%0], [%1], 16;\n" :: "r"(dst), "l"(src))
#define CP_COMMIT() asm volatile("cp.async.commit_group;\n" ::)

// ---------------------------------------------------------------------------
// Pre-pass: round fp32 -> tf32 (rna). One kernel for x, one fused for 4 weights.
// ---------------------------------------------------------------------------
__global__ void cvt_rna_kernel(const float4* __restrict__ src,
                               float4* __restrict__ dst, int n4) {
    int i = blockIdx.x * 256 + threadIdx.x;
    if (i < n4) {
        float4 v = src[i];
        float4 o;
        o.x = rna(v.x); o.y = rna(v.y); o.z = rna(v.z); o.w = rna(v.w);
        dst[i] = o;
    }
}

__global__ void cvt_rna_w4(const float4* __restrict__ s0, const float4* __restrict__ s1,
                           const float4* __restrict__ s2, const float4* __restrict__ s3,
                           float4* __restrict__ d0, float4* __restrict__ d1,
                           float4* __restrict__ d2, float4* __restrict__ d3, int n4) {
    const float4* s = (blockIdx.y == 0) ? s0 : (blockIdx.y == 1) ? s1
                      : (blockIdx.y == 2) ? s2 : s3;
    float4* d = (blockIdx.y == 0) ? d0 : (blockIdx.y == 1) ? d1
                : (blockIdx.y == 2) ? d2 : d3;
    int i = blockIdx.x * 256 + threadIdx.x;
    if (i < n4) {
        float4 v = s[i];
        float4 o;
        o.x = rna(v.x); o.y = rna(v.y); o.z = rna(v.z); o.w = rna(v.w);
        d[i] = o;
    }
}

// ---------------------------------------------------------------------------
// GEMM: C[m][n] = sum_k A[m][k] * W[n][k]  (tf32 HMMA)
// ROUND: rna outputs (Q/K/V feeding tf32 attention).
// PERM:  write columns interleaved within 8-groups [c0,c4,c1,c5,c2,c6,c3,c7]
//        so the attention kernel can fetch (t, t+4) fragment pairs as LDS.64.
// ---------------------------------------------------------------------------
template <bool ROUND, bool PERM>
__device__ __forceinline__ void gemm_body(const float* __restrict__ A,
                                          const float* __restrict__ W,
                                          float* __restrict__ C,
                                          int m0, int n0) {
    constexpr int K = DM, N = DM;
    extern __shared__ uint32_t sm[];

    const int tid  = threadIdx.x;
    const int lane = tid & 31;
    const int wid  = tid >> 5;
    const int g    = lane >> 2;
    const int t    = lane & 3;
    const int wm   = wid >> 2;
    const int wn   = wid & 3;

    const int f  = tid & 7;
    const int r0 = tid >> 3;

    const uint32_t smem_base = (uint32_t)__cvta_generic_to_shared(sm);

    float c[4][4][4];
#pragma unroll
    for (int mi = 0; mi < 4; mi++)
#pragma unroll
        for (int ni = 0; ni < 4; ni++)
#pragma unroll
            for (int e = 0; e < 4; e++) c[mi][ni][e] = 0.0f;

    auto issue_tile = [&](int j, int buf) {
        uint32_t base = smem_base + buf * (8192u * 4u);
#pragma unroll
        for (int p = 0; p < 4; p++) {
            int r = r0 + p * 32;
            uint32_t off = (uint32_t)(r * 32 + ((f ^ (r & 7)) << 2)) * 4u;
            CP_ASYNC16(base + off,           A + (size_t)(m0 + r) * K + j * 32 + f * 4);
            CP_ASYNC16(base + 16384u + off,  W + (size_t)(n0 + r) * K + j * 32 + f * 4);
        }
        CP_COMMIT();
    };

    issue_tile(0, 0);

    constexpr int NIT = K / 32;
    for (int it = 0; it < NIT; ++it) {
        if (it + 1 < NIT) {
            issue_tile(it + 1, (it + 1) & 1);
            asm volatile("cp.async.wait_group 1;\n" ::);
        } else {
            asm volatile("cp.async.wait_group 0;\n" ::);
        }
        __syncthreads();

        const uint32_t* As = sm + (it & 1) * 8192;
        const uint32_t* Bs = As + 4096;

#pragma unroll
        for (int k4 = 0; k4 < 8; k4 += 2) {
            uint32_t af[4][4];
#pragma unroll
            for (int mi = 0; mi < 4; mi++) {
                int r1 = wm * 64 + mi * 16 + g;
                int r2 = r1 + 8;
                int s0 = (k4 ^ g) << 2;
                int s1 = ((k4 + 1) ^ g) << 2;
                af[mi][0] = As[r1 * 32 + s0 + t];
                af[mi][1] = As[r2 * 32 + s0 + t];
                af[mi][2] = As[r1 * 32 + s1 + t];
                af[mi][3] = As[r2 * 32 + s1 + t];
            }
            uint32_t bf[4][2];
#pragma unroll
            for (int ni = 0; ni < 4; ni++) {
                int rn = wn * 32 + ni * 8 + g;
                int s0 = (k4 ^ g) << 2;
                int s1 = ((k4 + 1) ^ g) << 2;
                bf[ni][0] = Bs[rn * 32 + s0 + t];
                bf[ni][1] = Bs[rn * 32 + s1 + t];
            }
#pragma unroll
            for (int mi = 0; mi < 4; mi++)
#pragma unroll
                for (int ni = 0; ni < 4; ni++)
                    mma_tf32(c[mi][ni],
                             af[mi][0], af[mi][1], af[mi][2], af[mi][3],
                             bf[ni][0], bf[ni][1]);
        }
        __syncthreads();
    }

    // permuted positions for this thread's two columns (j=2t, j=2t+1)
    const int p1 = (t < 2) ? 4 * t     : 4 * t - 7;
    const int p2 = (t < 2) ? 4 * t + 2 : 4 * t - 5;

#pragma unroll
    for (int mi = 0; mi < 4; mi++) {
        int row = m0 + wm * 64 + mi * 16 + g;
#pragma unroll
        for (int ni = 0; ni < 4; ni++) {
            float e0 = c[mi][ni][0], e1 = c[mi][ni][1];
            float e2 = c[mi][ni][2], e3 = c[mi][ni][3];
            if (ROUND) { e0 = rna(e0); e1 = rna(e1); e2 = rna(e2); e3 = rna(e3); }
            if (PERM) {
                int base = n0 + wn * 32 + ni * 8;
                C[(size_t)row * N + base + p1]       = e0;
                C[(size_t)row * N + base + p2]       = e1;
                C[(size_t)(row + 8) * N + base + p1] = e2;
                C[(size_t)(row + 8) * N + base + p2] = e3;
            } else {
                int col = n0 + wn * 32 + ni * 8 + 2 * t;
                *(float2*)(C + (size_t)row * N + col)       = make_float2(e0, e1);
                *(float2*)(C + (size_t)(row + 8) * N + col) = make_float2(e2, e3);
            }
        }
    }
}

__global__ __launch_bounds__(256) void gemm_tf32(const float* __restrict__ A,
                                                 const float* __restrict__ W,
                                                 float* __restrict__ C) {
    gemm_body<false, false>(A, W, C, blockIdx.y * 128, blockIdx.x * 128);
}

__global__ __launch_bounds__(256) void gemm_qkv(const float* __restrict__ X,
                                                const float* __restrict__ Wq,
                                                const float* __restrict__ Wk,
                                                const float* __restrict__ Wv,
                                                float* __restrict__ Q,
                                                float* __restrict__ Ko,
                                                float* __restrict__ V) {
    if (blockIdx.z == 2) {
        // V: normal column order (PV fragment reads are scalar anyway)
        gemm_body<true, false>(X, Wv, V, blockIdx.y * 128, blockIdx.x * 128);
    } else if (blockIdx.z == 0) {
        gemm_body<true, true>(X, Wq, Q, blockIdx.y * 128, blockIdx.x * 128);
    } else {
        gemm_body<true, true>(X, Wk, Ko, blockIdx.y * 128, blockIdx.x * 128);
    }
}

// ---------------------------------------------------------------------------
// Tensor-core flash attention, cp.async double-buffered K/V.
// Q/K stored column-interleaved (GEMM epilogue) -> fragment pairs are LDS.64.
// All tiles pad-72 (stride ≡ 8 mod 32):
//   Q/K frag (LDS.64): banks 8g+2t+{0,1} -> conflict-free per half-warp.
//   V frag (LDS.32):  banks 8t+g -> conflict-free.
// Dynamic smem: (128*72 + 2*64*72 + 2*64*72)*4 = 110592 B -> 2 CTAs/SM.
// ---------------------------------------------------------------------------
constexpr int PAD = 72;
constexpr int ATTN_SMEM = (128 * PAD + 2 * 64 * PAD + 2 * 64 * PAD) * 4;

__global__ __launch_bounds__(256, 2) void attn_mma(const float* __restrict__ Q,
                                                   const float* __restrict__ Kg,
                                                   const float* __restrict__ V,
                                                   float* __restrict__ O) {
    extern __shared__ float smf[];
    float* Qs = smf;                              // [128][PAD]
    float* Kb = smf + 128 * PAD;                  // 2 x [64][PAD]
    float* Vb = Kb + 2 * 64 * PAD;                // 2 x [64][PAD]
    const uint32_t smem_base = (uint32_t)__cvta_generic_to_shared(smf);
    const uint32_t kb_base   = smem_base + 128 * PAD * 4;
    const uint32_t vb_base   = kb_base + 2 * 64 * PAD * 4;

    const int tid  = threadIdx.x;
    const int lane = tid & 31;
    const int w    = tid >> 5;       // warp 0..7 -> q-rows w*16..w*16+15
    const int g    = lane >> 2;      // 0..7
    const int t    = lane & 3;       // 0..3

    const int qi = (SQ / 128 - 1) - blockIdx.x;   // heavy tiles first
    const int h  = blockIdx.y;
    const int b  = blockIdx.z;
    const int q0 = qi * 128;

    const int cr = tid >> 4;             // 0..15 copy row
    const int cc = (tid & 15) * 4;       // 0..60 copy col (float4)

    // ---- async copy of one K/V 64-row block into buffer `buf` ----
    auto issue_kv = [&](int kt, int buf) {
        const float* kb = Kg + ((size_t)(b * SQ + kt * 64)) * DM + h * HD;
        const float* vb = V  + ((size_t)(b * SQ + kt * 64)) * DM + h * HD;
        uint32_t kdst = kb_base + (uint32_t)buf * (64 * PAD * 4);
        uint32_t vdst = vb_base + (uint32_t)buf * (64 * PAD * 4);
#pragma unroll
        for (int p = 0; p < 4; p++) {
            int r = cr + p * 16;
            CP_ASYNC16(kdst + (uint32_t)(r * PAD + cc) * 4, kb + (size_t)r * DM + cc);
            CP_ASYNC16(vdst + (uint32_t)(r * PAD + cc) * 4, vb + (size_t)r * DM + cc);
        }
        CP_COMMIT();
    };

    // ---- prologue: Q tile + first two K/V blocks ----
    {
        const float* qb = Q + ((size_t)(b * SQ + q0)) * DM + h * HD;
#pragma unroll
        for (int p = 0; p < 8; p++) {
            int r = cr + p * 16;
            CP_ASYNC16(smem_base + (uint32_t)(r * PAD + cc) * 4, qb + (size_t)r * DM + cc);
        }
    }
    const int nkt = 2 * qi + 2;
    issue_kv(0, 0);                 // commits Q + K0 + V0 as group 0
    if (nkt > 1) issue_kv(1, 1);    // group 1

    float of[8][4];
    float m_r[2] = {-1e30f, -1e30f};
    float l_r[2] = {0.0f, 0.0f};
#pragma unroll
    for (int n = 0; n < 8; n++)
#pragma unroll
        for (int e = 0; e < 4; e++) of[n][e] = 0.0f;

    const int rowA = q0 + w * 16 + g;
    const int rowB = rowA + 8;

    for (int kt = 0; kt < nkt; kt++) {
        if (kt + 1 < nkt) asm volatile("cp.async.wait_group 1;\n" ::);
        else              asm volatile("cp.async.wait_group 0;\n" ::);
        __syncthreads();

        const int buf = kt & 1;
        const float* Kc = Kb + buf * (64 * PAD);
        const float* Vc = Vb + buf * (64 * PAD);

        // warp fully above diagonal in this key block -> skip compute
        if (!(kt * 64 > q0 + w * 16 + 15)) {
            const bool diag = (kt >= 2 * qi);

            // ---- S = Q K^T (LDS.64 fragment pairs via interleaved columns) ----
            float s[8][4];
#pragma unroll
            for (int n = 0; n < 8; n++)
#pragma unroll
                for (int e = 0; e < 4; e++) s[n][e] = 0.0f;

#pragma unroll
            for (int kc = 0; kc < 8; kc++) {
                const float* qrow = &Qs[(w * 16 + g) * PAD + kc * 8 + 2 * t];
                uint2 qa0 = *(const uint2*)qrow;               // (col t, col t+4), row g
                uint2 qa1 = *(const uint2*)(qrow + 8 * PAD);   // row g+8
#pragma unroll
                for (int n = 0; n < 8; n++) {
                    uint2 kb2 = *(const uint2*)&Kc[(n * 8 + g) * PAD + kc * 8 + 2 * t];
                    mma_tf32(s[n], qa0.x, qa1.x, qa0.y, qa1.y, kb2.x, kb2.y);
                }
            }

            // ---- scale + causal mask ----
            const float sc = 0.125f;
#pragma unroll
            for (int n = 0; n < 8; n++) {
                int c0 = kt * 64 + n * 8 + 2 * t;
                s[n][0] *= sc; s[n][1] *= sc; s[n][2] *= sc; s[n][3] *= sc;
                if (diag) {
                    if (c0     > rowA) s[n][0] = -1e30f;
                    if (c0 + 1 > rowA) s[n][1] = -1e30f;
                    if (c0     > rowB) s[n][2] = -1e30f;
                    if (c0 + 1 > rowB) s[n][3] = -1e30f;
                }
            }

            // ---- online softmax ----
            float mA = -1e30f, mB = -1e30f;
#pragma unroll
            for (int n = 0; n < 8; n++) {
                mA = fmaxf(mA, fmaxf(s[n][0], s[n][1]));
                mB = fmaxf(mB, fmaxf(s[n][2], s[n][3]));
            }
            mA = fmaxf(mA, __shfl_xor_sync(0xffffffffu, mA, 1));
            mA = fmaxf(mA, __shfl_xor_sync(0xffffffffu, mA, 2));
            mB = fmaxf(mB, __shfl_xor_sync(0xffffffffu, mB, 1));
            mB = fmaxf(mB, __shfl_xor_sync(0xffffffffu, mB, 2));

            float nmA = fmaxf(m_r[0], mA), nmB = fmaxf(m_r[1], mB);
            float corrA = __expf(m_r[0] - nmA), corrB = __expf(m_r[1] - nmB);
            float sumA = 0.0f, sumB = 0.0f;
#pragma unroll
            for (int n = 0; n < 8; n++) {
                s[n][0] = __expf(s[n][0] - nmA);
                s[n][1] = __expf(s[n][1] - nmA);
                s[n][2] = __expf(s[n][2] - nmB);
                s[n][3] = __expf(s[n][3] - nmB);
                sumA += s[n][0] + s[n][1];
                sumB += s[n][2] + s[n][3];
            }
            sumA += __shfl_xor_sync(0xffffffffu, sumA, 1);
            sumA += __shfl_xor_sync(0xffffffffu, sumA, 2);
            sumB += __shfl_xor_sync(0xffffffffu, sumB, 1);
            sumB += __shfl_xor_sync(0xffffffffu, sumB, 2);
            l_r[0] = l_r[0] * corrA + sumA;
            l_r[1] = l_r[1] * corrB + sumB;
            m_r[0] = nmA; m_r[1] = nmB;
#pragma unroll
            for (int n = 0; n < 8; n++) {
                of[n][0] *= corrA; of[n][1] *= corrA;
                of[n][2] *= corrB; of[n][3] *= corrB;
            }

            // ---- round P to tf32 ----
#pragma unroll
            for (int n = 0; n < 8; n++) {
                s[n][0] = rna(s[n][0]); s[n][1] = rna(s[n][1]);
                s[n][2] = rna(s[n][2]); s[n][3] = rna(s[n][3]);
            }

            // ---- O += P V : A-frag via shuffles, B-frag from row-major V ----
            const int sl0 = (lane & ~3) | (t >> 1);
            const int sl1 = sl0 + 2;
            const bool odd = (t & 1);
#pragma unroll
            for (int kc = 0; kc < 8; kc++) {
                float v00 = __shfl_sync(0xffffffffu, s[kc][0], sl0);
                float v01 = __shfl_sync(0xffffffffu, s[kc][1], sl0);
                float v10 = __shfl_sync(0xffffffffu, s[kc][0], sl1);
                float v11 = __shfl_sync(0xffffffffu, s[kc][1], sl1);
                float w00 = __shfl_sync(0xffffffffu, s[kc][2], sl0);
                float w01 = __shfl_sync(0xffffffffu, s[kc][3], sl0);
                float w10 = __shfl_sync(0xffffffffu, s[kc][2], sl1);
                float w11 = __shfl_sync(0xffffffffu, s[kc][3], sl1);
                uint32_t a0 = __float_as_uint(odd ? v01 : v00);
                uint32_t a2 = __float_as_uint(odd ? v11 : v10);
                uint32_t a1 = __float_as_uint(odd ? w01 : w00);
                uint32_t a3 = __float_as_uint(odd ? w11 : w10);
                const float* vr0 = &Vc[(kc * 8 + t) * PAD];
                const float* vr1 = &Vc[(kc * 8 + t + 4) * PAD];
#pragma unroll
                for (int n = 0; n < 8; n++) {
                    uint32_t b0 = __float_as_uint(vr0[n * 8 + g]);
                    uint32_t b1 = __float_as_uint(vr1[n * 8 + g]);
                    mma_tf32(of[n], a0, a1, a2, a3, b0, b1);
                }
            }
        }

        __syncthreads();   // all reads of buf done before refilling it
        if (kt + 2 < nkt) issue_kv(kt + 2, buf);
    }

    // ---- epilogue: normalize, round to tf32 (feeds o-proj GEMM), store ----
    float invA = 1.0f / l_r[0];
    float invB = 1.0f / l_r[1];
    float* obA = O + ((size_t)(b * SQ + q0 + w * 16 + g)) * DM + h * HD;
    float* obB = obA + (size_t)8 * DM;
#pragma unroll
    for (int n = 0; n < 8; n++) {
        int c = n * 8 + 2 * t;
        *(float2*)(obA + c) = make_float2(rna(of[n][0] * invA), rna(of[n][1] * invA));
        *(float2*)(obB + c) = make_float2(rna(of[n][2] * invB), rna(of[n][3] * invB));
    }
}

// ---------------------------------------------------------------------------
extern "C" void kernel_launch(void* const* d_in, const int* in_sizes, int n_in,
                              void* d_out, int out_size) {
    const float* wq = (const float*)d_in[0];
    const float* wk = (const float*)d_in[1];
    const float* wv = (const float*)d_in[2];
    const float* wo = (const float*)d_in[3];
    const float* x  = (const float*)d_in[4];
    float* out = (float*)d_out;

    float *q, *k, *v, *a, *xc, *wc;
    cudaGetSymbolAddress((void**)&q,  g_q);
    cudaGetSymbolAddress((void**)&k,  g_k);
    cudaGetSymbolAddress((void**)&v,  g_v);
    cudaGetSymbolAddress((void**)&a,  g_attn);
    cudaGetSymbolAddress((void**)&xc, g_xc);
    cudaGetSymbolAddress((void**)&wc, g_wc);
    float* wc0 = wc;
    float* wc1 = wc + DM * DM;
    float* wc2 = wc + 2 * DM * DM;
    float* wc3 = wc + 3 * DM * DM;

    cudaFuncSetAttribute(gemm_tf32, cudaFuncAttributeMaxDynamicSharedMemorySize, 65536);
    cudaFuncSetAttribute(gemm_qkv,  cudaFuncAttributeMaxDynamicSharedMemorySize, 65536);
    cudaFuncSetAttribute(attn_mma,  cudaFuncAttributeMaxDynamicSharedMemorySize, ATTN_SMEM);

    int n4x = MT * DM / 4;
    int n4w = DM * DM / 4;
    cvt_rna_kernel<<<(n4x + 255) / 256, 256>>>((const float4*)x, (float4*)xc, n4x);
    cvt_rna_w4<<<dim3((n4w + 255) / 256, 4), 256>>>(
        (const float4*)wq, (const float4*)wk, (const float4*)wv, (const float4*)wo,
        (float4*)wc0, (float4*)wc1, (float4*)wc2, (float4*)wc3, n4w);

    dim3 gq(DM / 128, MT / 128, 3);
    gemm_qkv<<<gq, 256, 65536>>>(xc, wc0, wc1, wc2, q, k, v);

    attn_mma<<<dim3(SQ / 128, NH, BB), 256, ATTN_SMEM>>>(q, k, v, a);

    dim3 gg(DM / 128, MT / 128);
    gemm_tf32<<<gg, 256, 65536>>>(a, wc3, out);
}